// round 15
// baseline (speedup 1.0000x reference)
#include <cuda_runtime.h>
#include <cuda_bf16.h>
#include <cstdint>
#include <cstddef>

// ---------------- problem constants ----------------
#define BATCH 4
#define SEQ   2048
#define DMODEL 1024
#define NHEADS 16
#define HDIM   64
#define DFF    4096
#define MROWS  (BATCH*SEQ)          // 8192
#define LN_EPS 1e-5f

typedef __nv_bfloat16  bf16;
typedef __nv_bfloat162 bf162;

// ---------------- scratch (device globals; no allocations allowed) ----------
__device__ bf16  g_qkvb[(size_t)MROWS * 3 * DMODEL];
__device__ bf16  g_h_hi[(size_t)MROWS * DMODEL];
__device__ bf16  g_h_lo[(size_t)MROWS * DMODEL];
__device__ bf16  g_o_hi[(size_t)MROWS * DMODEL];
__device__ bf16  g_o_lo[(size_t)MROWS * DMODEL];
__device__ bf16  g_h2_hi[(size_t)MROWS * DFF];
__device__ bf16  g_h2_lo[(size_t)MROWS * DFF];
__device__ bf16  g_wqkv_hi[(size_t)3*DMODEL*DMODEL];
__device__ bf16  g_wout_hi[(size_t)DMODEL*DMODEL];
__device__ bf16  g_wout_lo[(size_t)DMODEL*DMODEL];
__device__ bf16  g_wfc1_hi[(size_t)DFF*DMODEL];
__device__ bf16  g_wfc1_lo[(size_t)DFF*DMODEL];
__device__ bf16  g_wfc2_hi[(size_t)DMODEL*DFF];

// ---------------- helpers ----------------
__device__ __forceinline__ float gelu_exact(float x) {
    return 0.5f * x * (1.0f + erff(x * 0.70710678118654752f));
}
__device__ __forceinline__ void split2(float v, bf16& h, bf16& l) {
    h = __float2bfloat16(v);
    l = __float2bfloat16(v - __bfloat162float(h));
}
__device__ __forceinline__ uint32_t pk2(float a, float b) {
    bf162 t = __floats2bfloat162_rn(a, b);
    return *(uint32_t*)&t;
}
__device__ __forceinline__ void cp16(void* dst_smem, const void* src_gmem) {
    unsigned s = (unsigned)__cvta_generic_to_shared(dst_smem);
    asm volatile("cp.async.cg.shared.global [%0], [%1], 16;" :: "r"(s), "l"(src_gmem) : "memory");
}
__device__ __forceinline__ void cp_commit() {
    asm volatile("cp.async.commit_group;" ::: "memory");
}
template<int N>
__device__ __forceinline__ void cp_wait() {
    asm volatile("cp.async.wait_group %0;" :: "n"(N) : "memory");
}
__device__ __forceinline__ void mma16816(float* c, const uint32_t* a, const uint32_t* b) {
    asm volatile(
        "mma.sync.aligned.m16n8k16.row.col.f32.bf16.bf16.f32 "
        "{%0,%1,%2,%3}, {%4,%5,%6,%7}, {%8,%9}, {%0,%1,%2,%3};"
        : "+f"(c[0]), "+f"(c[1]), "+f"(c[2]), "+f"(c[3])
        : "r"(a[0]), "r"(a[1]), "r"(a[2]), "r"(a[3]), "r"(b[0]), "r"(b[1]));
}
__device__ __forceinline__ void ldsm_x4(uint32_t& r0, uint32_t& r1, uint32_t& r2, uint32_t& r3,
                                        const void* p) {
    uint32_t a = (uint32_t)__cvta_generic_to_shared(p);
    asm volatile("ldmatrix.sync.aligned.m8n8.x4.shared.b16 {%0,%1,%2,%3}, [%4];"
                 : "=r"(r0), "=r"(r1), "=r"(r2), "=r"(r3) : "r"(a));
}
__device__ __forceinline__ void ldsm_x4_t(uint32_t& r0, uint32_t& r1, uint32_t& r2, uint32_t& r3,
                                          const void* p) {
    uint32_t a = (uint32_t)__cvta_generic_to_shared(p);
    asm volatile("ldmatrix.sync.aligned.m8n8.x4.trans.shared.b16 {%0,%1,%2,%3}, [%4];"
                 : "=r"(r0), "=r"(r1), "=r"(r2), "=r"(r3) : "r"(a));
}

// ---------------- weight split kernel (fp32 -> bf16 hi/lo) -----------------
__global__ __launch_bounds__(256) void split_kernel(
    const float* __restrict__ in, bf16* __restrict__ hi, bf16* __restrict__ lo)
{
    int i = blockIdx.x * blockDim.x + threadIdx.x;
    float4 v = ((const float4*)in)[i];
    bf16 h0,h1,h2,h3,l0,l1,l2,l3;
    split2(v.x,h0,l0); split2(v.y,h1,l1); split2(v.z,h2,l2); split2(v.w,h3,l3);
    bf162 ha; ha.x=h0; ha.y=h1;  bf162 hb; hb.x=h2; hb.y=h3;
    bf162 la; la.x=l0; la.y=l1;  bf162 lb; lb.x=l2; lb.y=l3;
    ((bf162*)hi)[2*i]   = ha; ((bf162*)hi)[2*i+1] = hb;
    ((bf162*)lo)[2*i]   = la; ((bf162*)lo)[2*i+1] = lb;
}
__global__ __launch_bounds__(256) void cvt_kernel(
    const float* __restrict__ in, bf16* __restrict__ hi)
{
    int i = blockIdx.x * blockDim.x + threadIdx.x;
    float4 v = ((const float4*)in)[i];
    uint2 o;
    o.x = pk2(v.x, v.y);
    o.y = pk2(v.z, v.w);
    ((uint2*)hi)[i] = o;
}

// ---------------- LayerNorm -> bf16 (hi, optional lo) ----------------------
template<bool WLO>
__global__ __launch_bounds__(256) void layernorm_split_kernel(
    const float* __restrict__ x, const float* __restrict__ g,
    const float* __restrict__ b, bf16* __restrict__ hi, bf16* __restrict__ lo)
{
    int row = blockIdx.x;
    const float4* xr = (const float4*)(x + (size_t)row * DMODEL);
    float4 v = xr[threadIdx.x];
    float s  = v.x + v.y + v.z + v.w;
    float sq = v.x*v.x + v.y*v.y + v.z*v.z + v.w*v.w;
    #pragma unroll
    for (int o = 16; o; o >>= 1) {
        s  += __shfl_xor_sync(0xffffffffu, s,  o);
        sq += __shfl_xor_sync(0xffffffffu, sq, o);
    }
    __shared__ float ss[8], ssq[8];
    int w = threadIdx.x >> 5, lane = threadIdx.x & 31;
    if (lane == 0) { ss[w] = s; ssq[w] = sq; }
    __syncthreads();
    float st = 0.f, sqt = 0.f;
    #pragma unroll
    for (int k = 0; k < 8; k++) { st += ss[k]; sqt += ssq[k]; }
    float mean = st * (1.0f / DMODEL);
    float var  = sqt * (1.0f / DMODEL) - mean * mean;
    float inv  = rsqrtf(var + LN_EPS);
    float4 gg = ((const float4*)g)[threadIdx.x];
    float4 bb = ((const float4*)b)[threadIdx.x];
    float o0 = (v.x - mean) * inv * gg.x + bb.x;
    float o1 = (v.y - mean) * inv * gg.y + bb.y;
    float o2 = (v.z - mean) * inv * gg.z + bb.z;
    float o3 = (v.w - mean) * inv * gg.w + bb.w;
    bf16 h0,h1,h2,h3,l0,l1,l2,l3;
    split2(o0,h0,l0); split2(o1,h1,l1); split2(o2,h2,l2); split2(o3,h3,l3);
    bf162 ha; ha.x=h0; ha.y=h1;  bf162 hb; hb.x=h2; hb.y=h3;
    bf162* hp = (bf162*)(hi + (size_t)row * DMODEL);
    hp[2*threadIdx.x] = ha; hp[2*threadIdx.x+1] = hb;
    if (WLO) {
        bf162 la; la.x=l0; la.y=l1;  bf162 lb; lb.x=l2; lb.y=l3;
        bf162* lp = (bf162*)(lo + (size_t)row * DMODEL);
        lp[2*threadIdx.x] = la; lp[2*threadIdx.x+1] = lb;
    }
}

// ---------------- bf16 split tensor-core GEMM (2-stage, ldmatrix) ----------
// MODE 1: gelu -> split bf16; MODE 2: fp32 bias+resid; MODE 3: bf16 out
// PASSES 3: Ah*Bh+Al*Bh+Ah*Bl (4 tiles/stage); 2: 3 tiles; 1: 2 tiles
#define BM 128
#define BN 128
#define BK 32
#define SSTRIDE 40
#define TILE_B  (BM * SSTRIDE * 2)

template<int MODE, int PASSES>
__global__ __launch_bounds__(256, 2) void gemm_bf16x3(
    const bf16* __restrict__ Ah, const bf16* __restrict__ Al,
    const bf16* __restrict__ Bh, const bf16* __restrict__ Bl,
    const float* __restrict__ bias, const float* __restrict__ R,
    float* __restrict__ C, bf16* __restrict__ Chi, bf16* __restrict__ Clo,
    int M, int N, int K)
{
    extern __shared__ char smem[];
    constexpr int NTILES = (PASSES == 3) ? 4 : ((PASSES == 2) ? 3 : 2);
    constexpr int STG_B  = NTILES * TILE_B;
    constexpr int SLOT_BH = (PASSES >= 2) ? 2 : 1;
    const int tid  = threadIdx.x;
    const int bm = blockIdx.y * BM, bn = blockIdx.x * BN;
    const int warp = tid >> 5, lane = tid & 31;
    const int wm = warp >> 2, wn = warp & 3;
    const int gg = lane >> 2, qt = lane & 3;
    const int g8 = lane >> 3, lr = lane & 7;

    const bf16* gmat0 = Ah + (size_t)bm * K;
    const bf16* gmat1 = (PASSES >= 2) ? (Al + (size_t)bm * K) : nullptr;
    const bf16* gmat2 = Bh + (size_t)bn * K;
    const bf16* gmat3 = (PASSES == 3) ? (Bl + (size_t)bn * K) : nullptr;

    float acc[4][4][4];
    #pragma unroll
    for (int i = 0; i < 4; i++)
        #pragma unroll
        for (int j = 0; j < 4; j++)
            #pragma unroll
            for (int q = 0; q < 4; q++) acc[i][j][q] = 0.f;

    const int NK = K / BK;

    auto issue = [&](int k0, int st) {
        char* sb = smem + st * STG_B;
        #pragma unroll
        for (int c = 0; c < 2; c++) {
            int chunk = tid + c * 256;
            int row = chunk >> 2, col = chunk & 3;
            size_t goff = (size_t)row * K + k0 + col * 8;
            char*  sdst = sb + row * (SSTRIDE * 2) + col * 16;
            cp16(sdst + 0 * TILE_B, gmat0 + goff);
            if (PASSES >= 2) cp16(sdst + 1 * TILE_B, gmat1 + goff);
            cp16(sdst + SLOT_BH * TILE_B, gmat2 + goff);
            if (PASSES == 3) cp16(sdst + 3 * TILE_B, gmat3 + goff);
        }
    };

    issue(0, 0); cp_commit();

    const int a_row = (g8 & 1) * 8 + lr;
    const int a_col = (g8 >> 1) * 8;
    const int b_row = (g8 >> 1) * 8 + lr;
    const int b_col = (g8 & 1) * 8;

    for (int ks = 0; ks < NK; ks++) {
        const int cur = ks & 1;
        if (ks + 1 < NK) { issue((ks + 1) * BK, cur ^ 1); cp_commit(); cp_wait<1>(); }
        else             { cp_wait<0>(); }
        __syncthreads();

        const bf16* sAh = (const bf16*)(smem + cur * STG_B);
        const bf16* sAl = sAh + BM * SSTRIDE;
        const bf16* sBh = sAh + SLOT_BH * BM * SSTRIDE;
        const bf16* sBl = sAh + 3 * BM * SSTRIDE;

        #pragma unroll
        for (int kk = 0; kk < BK; kk += 16) {
            uint32_t afr[4][4], bfr[4][2];
            #pragma unroll
            for (int mt = 0; mt < 4; mt++) {
                const bf16* p = sAh + (wm*64 + mt*16 + a_row) * SSTRIDE + kk + a_col;
                ldsm_x4(afr[mt][0], afr[mt][1], afr[mt][2], afr[mt][3], p);
            }
            #pragma unroll
            for (int np = 0; np < 2; np++) {
                const bf16* p = sBh + (wn*32 + np*16 + b_row) * SSTRIDE + kk + b_col;
                ldsm_x4(bfr[2*np][0], bfr[2*np][1], bfr[2*np+1][0], bfr[2*np+1][1], p);
            }
            #pragma unroll
            for (int mt = 0; mt < 4; mt++)
                #pragma unroll
                for (int nt = 0; nt < 4; nt++)
                    mma16816(acc[mt][nt], afr[mt], bfr[nt]);
            if (PASSES >= 2) {
                uint32_t afl[4][4];
                #pragma unroll
                for (int mt = 0; mt < 4; mt++) {
                    const bf16* p = sAl + (wm*64 + mt*16 + a_row) * SSTRIDE + kk + a_col;
                    ldsm_x4(afl[mt][0], afl[mt][1], afl[mt][2], afl[mt][3], p);
                }
                #pragma unroll
                for (int mt = 0; mt < 4; mt++)
                    #pragma unroll
                    for (int nt = 0; nt < 4; nt++)
                        mma16816(acc[mt][nt], afl[mt], bfr[nt]);
            }
            if (PASSES == 3) {
                #pragma unroll
                for (int np = 0; np < 2; np++) {
                    const bf16* p = sBl + (wn*32 + np*16 + b_row) * SSTRIDE + kk + b_col;
                    ldsm_x4(bfr[2*np][0], bfr[2*np][1], bfr[2*np+1][0], bfr[2*np+1][1], p);
                }
                #pragma unroll
                for (int mt = 0; mt < 4; mt++)
                    #pragma unroll
                    for (int nt = 0; nt < 4; nt++)
                        mma16816(acc[mt][nt], afr[mt], bfr[nt]);
            }
        }
        __syncthreads();
    }

    #pragma unroll
    for (int mt = 0; mt < 4; mt++) {
        #pragma unroll
        for (int nt = 0; nt < 4; nt++) {
            int r  = bm + wm * 64 + mt * 16 + gg;
            int c0 = bn + wn * 32 + nt * 8 + 2 * qt;
            float2 bv = *(const float2*)(bias + c0);
            float v00 = acc[mt][nt][0] + bv.x;
            float v01 = acc[mt][nt][1] + bv.y;
            float v10 = acc[mt][nt][2] + bv.x;
            float v11 = acc[mt][nt][3] + bv.y;
            if (MODE == 2) {
                float2 r0 = *(const float2*)(R + (size_t)r * N + c0);
                float2 r1 = *(const float2*)(R + (size_t)(r + 8) * N + c0);
                v00 += r0.x; v01 += r0.y; v10 += r1.x; v11 += r1.y;
            }
            if (MODE == 1) {
                v00 = gelu_exact(v00); v01 = gelu_exact(v01);
                v10 = gelu_exact(v10); v11 = gelu_exact(v11);
                bf16 h0,h1,h2,h3,l0,l1,l2,l3;
                split2(v00,h0,l0); split2(v01,h1,l1);
                split2(v10,h2,l2); split2(v11,h3,l3);
                bf162 pa; pa.x=h0; pa.y=h1;  bf162 pb; pb.x=h2; pb.y=h3;
                bf162 qa; qa.x=l0; qa.y=l1;  bf162 qb; qb.x=l2; qb.y=l3;
                *(bf162*)(Chi + (size_t)r * N + c0)       = pa;
                *(bf162*)(Chi + (size_t)(r + 8) * N + c0) = pb;
                *(bf162*)(Clo + (size_t)r * N + c0)       = qa;
                *(bf162*)(Clo + (size_t)(r + 8) * N + c0) = qb;
            } else if (MODE == 3) {
                uint32_t pa = pk2(v00, v01);
                uint32_t pb = pk2(v10, v11);
                *(uint32_t*)(Chi + (size_t)r * N + c0)       = pa;
                *(uint32_t*)(Chi + (size_t)(r + 8) * N + c0) = pb;
            } else {
                *(float2*)(C + (size_t)r * N + c0)       = make_float2(v00, v01);
                *(float2*)(C + (size_t)(r + 8) * N + c0) = make_float2(v10, v11);
            }
        }
    }
}

// ---------------- tensor-core causal flash attention (batch-chunked) -------
// b0: first batch of this chunk; gridDim.y covers NB batches (NB*16 head-rows).
#define KSTR 72

__global__ __launch_bounds__(256) void attn_mma_kernel(
    const bf16* __restrict__ qkvb, bf16* __restrict__ o_hi, bf16* __restrict__ o_lo,
    int b0)
{
    extern __shared__ char asmem[];
    bf16* Qs = (bf16*)asmem;
    bf16* Ks = Qs + 128 * KSTR;
    bf16* Vs = Ks + 2 * 64 * KSTR;

    const int tid = threadIdx.x;
    const int warp = tid >> 5, lane = tid & 31;
    const int gg = lane >> 2, qt = lane & 3;
    const int g8 = lane >> 3, lr = lane & 7;
    const int qt_blk = gridDim.x - 1 - blockIdx.x;      // heavy-first
    const int bh = blockIdx.y;
    const int b = b0 + (bh >> 4), h = bh & 15;
    const int q0 = qt_blk * 128;
    const size_t ROW = 3 * DMODEL;
    const bf16* qg = qkvb + (size_t)(b * SEQ) * ROW + h * HDIM;
    const bf16* kg = qg + DMODEL;
    const bf16* vg = qg + 2 * DMODEL;

    #pragma unroll
    for (int u = 0; u < 4; u++) {
        int idx = tid + u * 256;
        int r = idx >> 3, c = (idx & 7) * 8;
        *(uint4*)&Qs[r * KSTR + c] = *(const uint4*)(qg + (size_t)(q0 + r) * ROW + c);
    }
    __syncthreads();

    uint32_t qf[4][4];
    {
        const bf162 sc = __floats2bfloat162_rn(0.125f, 0.125f);
        #pragma unroll
        for (int kt = 0; kt < 4; kt++) {
            const bf16* p = &Qs[(warp * 16 + (g8 & 1) * 8 + lr) * KSTR + kt * 16 + (g8 >> 1) * 8];
            ldsm_x4(qf[kt][0], qf[kt][1], qf[kt][2], qf[kt][3], p);
            #pragma unroll
            for (int i = 0; i < 4; i++) {
                bf162 v = *(bf162*)&qf[kt][i];
                v = __hmul2(v, sc);
                qf[kt][i] = *(uint32_t*)&v;
            }
        }
    }

    float oacc[8][4];
    #pragma unroll
    for (int nt = 0; nt < 8; nt++)
        #pragma unroll
        for (int i = 0; i < 4; i++) oacc[nt][i] = 0.f;
    float m0 = -1e30f, m1 = -1e30f, l0 = 0.f, l1 = 0.f;

    const int ntiles = qt_blk * 2 + 2;
    const int wbase = q0 + warp * 16;
    const int wmax  = wbase + 15;

    auto issue = [&](int t, int st) {
        #pragma unroll
        for (int u = 0; u < 2; u++) {
            int idx = tid + u * 256;
            int r = idx >> 3, c = (idx & 7) * 8;
            size_t goff = (size_t)(t * 64 + r) * ROW + c;
            cp16(&Ks[st * 64 * KSTR + r * KSTR + c], kg + goff);
            cp16(&Vs[st * 64 * KSTR + r * KSTR + c], vg + goff);
        }
    };

    issue(0, 0); cp_commit();

    for (int t = 0; t < ntiles; t++) {
        const int cur = t & 1;
        if (t + 1 < ntiles) { issue(t + 1, cur ^ 1); cp_commit(); cp_wait<1>(); }
        else                { cp_wait<0>(); }
        __syncthreads();

        const int j0 = t * 64;
        if (j0 <= wmax) {
            const bf16* Kt = &Ks[cur * 64 * KSTR];
            const bf16* Vt = &Vs[cur * 64 * KSTR];

            float sacc[8][4];
            #pragma unroll
            for (int nt = 0; nt < 8; nt++)
                #pragma unroll
                for (int i = 0; i < 4; i++) sacc[nt][i] = 0.f;

            #pragma unroll
            for (int kt = 0; kt < 4; kt++) {
                uint32_t bfr[8][2];
                #pragma unroll
                for (int np = 0; np < 4; np++) {
                    const bf16* p = &Kt[(np * 16 + (g8 >> 1) * 8 + lr) * KSTR + kt * 16 + (g8 & 1) * 8];
                    ldsm_x4(bfr[2*np][0], bfr[2*np][1], bfr[2*np+1][0], bfr[2*np+1][1], p);
                }
                #pragma unroll
                for (int nt = 0; nt < 8; nt++)
                    mma16816(sacc[nt], qf[kt], bfr[nt]);
            }

            const int r0 = wbase + gg, r1 = r0 + 8;
            if (j0 + 63 > wbase) {
                #pragma unroll
                for (int nt = 0; nt < 8; nt++) {
                    int c0 = j0 + nt * 8 + 2 * qt, c1 = c0 + 1;
                    if (c0 > r0) sacc[nt][0] = -1e30f;
                    if (c1 > r0) sacc[nt][1] = -1e30f;
                    if (c0 > r1) sacc[nt][2] = -1e30f;
                    if (c1 > r1) sacc[nt][3] = -1e30f;
                }
            }

            float mx0 = -1e30f, mx1 = -1e30f;
            #pragma unroll
            for (int nt = 0; nt < 8; nt++) {
                mx0 = fmaxf(mx0, fmaxf(sacc[nt][0], sacc[nt][1]));
                mx1 = fmaxf(mx1, fmaxf(sacc[nt][2], sacc[nt][3]));
            }
            mx0 = fmaxf(mx0, __shfl_xor_sync(0xffffffffu, mx0, 1));
            mx0 = fmaxf(mx0, __shfl_xor_sync(0xffffffffu, mx0, 2));
            mx1 = fmaxf(mx1, __shfl_xor_sync(0xffffffffu, mx1, 1));
            mx1 = fmaxf(mx1, __shfl_xor_sync(0xffffffffu, mx1, 2));
            float mn0 = fmaxf(m0, mx0), mn1 = fmaxf(m1, mx1);
            float cr0 = __expf(m0 - mn0), cr1 = __expf(m1 - mn1);
            m0 = mn0; m1 = mn1;

            float ps0 = 0.f, ps1 = 0.f;
            uint32_t pa[4][4];
            #pragma unroll
            for (int np = 0; np < 4; np++) {
                float e00 = __expf(sacc[2*np  ][0] - mn0);
                float e01 = __expf(sacc[2*np  ][1] - mn0);
                float e02 = __expf(sacc[2*np  ][2] - mn1);
                float e03 = __expf(sacc[2*np  ][3] - mn1);
                float e10 = __expf(sacc[2*np+1][0] - mn0);
                float e11 = __expf(sacc[2*np+1][1] - mn0);
                float e12 = __expf(sacc[2*np+1][2] - mn1);
                float e13 = __expf(sacc[2*np+1][3] - mn1);
                ps0 += e00 + e01 + e10 + e11;
                ps1 += e02 + e03 + e12 + e13;
                pa[np][0] = pk2(e00, e01);
                pa[np][1] = pk2(e02, e03);
                pa[np][2] = pk2(e10, e11);
                pa[np][3] = pk2(e12, e13);
            }
            ps0 += __shfl_xor_sync(0xffffffffu, ps0, 1);
            ps0 += __shfl_xor_sync(0xffffffffu, ps0, 2);
            ps1 += __shfl_xor_sync(0xffffffffu, ps1, 1);
            ps1 += __shfl_xor_sync(0xffffffffu, ps1, 2);
            l0 = l0 * cr0 + ps0;
            l1 = l1 * cr1 + ps1;
            #pragma unroll
            for (int nt = 0; nt < 8; nt++) {
                oacc[nt][0] *= cr0; oacc[nt][1] *= cr0;
                oacc[nt][2] *= cr1; oacc[nt][3] *= cr1;
            }

            #pragma unroll
            for (int kt = 0; kt < 4; kt++) {
                uint32_t vfr[8][2];
                #pragma unroll
                for (int np = 0; np < 4; np++) {
                    const bf16* p = &Vt[(kt * 16 + (g8 & 1) * 8 + lr) * KSTR + np * 16 + (g8 >> 1) * 8];
                    ldsm_x4_t(vfr[2*np][0], vfr[2*np][1], vfr[2*np+1][0], vfr[2*np+1][1], p);
                }
                #pragma unroll
                for (int nt = 0; nt < 8; nt++)
                    mma16816(oacc[nt], pa[kt], vfr[nt]);
            }
        }
        __syncthreads();
    }

    float inv0 = 1.f / l0, inv1 = 1.f / l1;
    int grow0 = b * SEQ + wbase + gg;
    int grow1 = grow0 + 8;
    #pragma unroll
    for (int nt = 0; nt < 8; nt++) {
        int col = h * HDIM + nt * 8 + 2 * qt;
        float v00 = oacc[nt][0] * inv0, v01 = oacc[nt][1] * inv0;
        float v10 = oacc[nt][2] * inv1, v11 = oacc[nt][3] * inv1;
        bf16 h0,h1,h2,h3,l0b,l1b,l2b,l3b;
        split2(v00,h0,l0b); split2(v01,h1,l1b);
        split2(v10,h2,l2b); split2(v11,h3,l3b);
        bf162 pa; pa.x=h0; pa.y=h1;  bf162 pb; pb.x=h2; pb.y=h3;
        bf162 qa; qa.x=l0b; qa.y=l1b; bf162 qb; qb.x=l2b; qb.y=l3b;
        *(bf162*)(o_hi + (size_t)grow0 * DMODEL + col) = pa;
        *(bf162*)(o_hi + (size_t)grow1 * DMODEL + col) = pb;
        *(bf162*)(o_lo + (size_t)grow0 * DMODEL + col) = qa;
        *(bf162*)(o_lo + (size_t)grow1 * DMODEL + col) = qb;
    }
}

// ---------------- launch ----------------
extern "C" void kernel_launch(void* const* d_in, const int* in_sizes, int n_in,
                              void* d_out, int out_size)
{
    const float* x     = (const float*)d_in[0];
    const float* ln1_g = (const float*)d_in[1];
    const float* ln1_b = (const float*)d_in[2];
    const float* qkv_w = (const float*)d_in[3];
    const float* qkv_b = (const float*)d_in[4];
    const float* out_w = (const float*)d_in[5];
    const float* out_b = (const float*)d_in[6];
    const float* ln2_g = (const float*)d_in[7];
    const float* ln2_b = (const float*)d_in[8];
    const float* fc1_w = (const float*)d_in[9];
    const float* fc1_b = (const float*)d_in[10];
    const float* fc2_w = (const float*)d_in[11];
    const float* fc2_b = (const float*)d_in[12];
    float* out = (float*)d_out;

    static bf16 *p_qkvb = nullptr;
    static bf16 *p_h_hi, *p_h_lo, *p_o_hi, *p_o_lo, *p_h2_hi, *p_h2_lo;
    static bf16 *p_wqkv_hi, *p_wout_hi, *p_wout_lo;
    static bf16 *p_wfc1_hi, *p_wfc1_lo, *p_wfc2_hi;
    static cudaStream_t s2 = nullptr;
    static cudaEvent_t e0, e_cvtq, e_cvt_all, e_attn0, e_out0;
    if (!p_qkvb) {
        cudaGetSymbolAddress((void**)&p_qkvb,   g_qkvb);
        cudaGetSymbolAddress((void**)&p_h_hi,   g_h_hi);
        cudaGetSymbolAddress((void**)&p_h_lo,   g_h_lo);
        cudaGetSymbolAddress((void**)&p_o_hi,   g_o_hi);
        cudaGetSymbolAddress((void**)&p_o_lo,   g_o_lo);
        cudaGetSymbolAddress((void**)&p_h2_hi,  g_h2_hi);
        cudaGetSymbolAddress((void**)&p_h2_lo,  g_h2_lo);
        cudaGetSymbolAddress((void**)&p_wqkv_hi, g_wqkv_hi);
        cudaGetSymbolAddress((void**)&p_wout_hi, g_wout_hi);
        cudaGetSymbolAddress((void**)&p_wout_lo, g_wout_lo);
        cudaGetSymbolAddress((void**)&p_wfc1_hi, g_wfc1_hi);
        cudaGetSymbolAddress((void**)&p_wfc1_lo, g_wfc1_lo);
        cudaGetSymbolAddress((void**)&p_wfc2_hi, g_wfc2_hi);
        cudaStreamCreateWithFlags(&s2, cudaStreamNonBlocking);
        cudaEventCreateWithFlags(&e0,        cudaEventDisableTiming);
        cudaEventCreateWithFlags(&e_cvtq,    cudaEventDisableTiming);
        cudaEventCreateWithFlags(&e_cvt_all, cudaEventDisableTiming);
        cudaEventCreateWithFlags(&e_attn0,   cudaEventDisableTiming);
        cudaEventCreateWithFlags(&e_out0,    cudaEventDisableTiming);
    }

    const int SMEM_G3 = 2 * (4 * TILE_B);                 // 81920
    const int SMEM_G2 = 2 * (3 * TILE_B);                 // 61440
    const int SMEM_G1 = 2 * (2 * TILE_B);                 // 40960
    const int SMEM_ATTN = (128 + 2*64 + 2*64) * KSTR * 2; // 55296
    cudaFuncSetAttribute((const void*)gemm_bf16x3<1,3>, cudaFuncAttributeMaxDynamicSharedMemorySize, SMEM_G3);
    cudaFuncSetAttribute((const void*)gemm_bf16x3<2,3>, cudaFuncAttributeMaxDynamicSharedMemorySize, SMEM_G3);
    cudaFuncSetAttribute((const void*)gemm_bf16x3<2,2>, cudaFuncAttributeMaxDynamicSharedMemorySize, SMEM_G2);
    cudaFuncSetAttribute((const void*)gemm_bf16x3<3,1>, cudaFuncAttributeMaxDynamicSharedMemorySize, SMEM_G1);
    cudaFuncSetAttribute((const void*)attn_mma_kernel,  cudaFuncAttributeMaxDynamicSharedMemorySize, SMEM_ATTN);

    const int HALF = MROWS / 2;                 // 4096 rows = batches {0,1} / {2,3}

    // ---- fork: weight converts on side stream (off the critical path) ----
    cudaEventRecord(e0, 0);
    cudaStreamWaitEvent(s2, e0, 0);
    cvt_kernel<<<(3*DMODEL*DMODEL)/4/256, 256, 0, s2>>>(qkv_w, p_wqkv_hi);
    cudaEventRecord(e_cvtq, s2);
    split_kernel<<<(DMODEL*DMODEL)/4/256, 256, 0, s2>>>(out_w, p_wout_hi, p_wout_lo);
    split_kernel<<<(DFF*DMODEL)/4/256,    256, 0, s2>>>(fc1_w, p_wfc1_hi, p_wfc1_lo);
    cvt_kernel  <<<(DMODEL*DFF)/4/256,    256, 0, s2>>>(fc2_w, p_wfc2_hi);
    cudaEventRecord(e_cvt_all, s2);

    // ---- main stream: critical path ----
    layernorm_split_kernel<false><<<MROWS, 256>>>(x, ln1_g, ln1_b, p_h_hi, nullptr);
    cudaStreamWaitEvent(0, e_cvtq, 0);
    gemm_bf16x3<3,1><<<dim3(3*DMODEL/BN, MROWS/BM), 256, SMEM_G1>>>(
        p_h_hi, nullptr, p_wqkv_hi, nullptr, qkv_b, nullptr,
        nullptr, p_qkvb, nullptr, MROWS, 3*DMODEL, DMODEL);

    // attention chunk 0 (batches 0,1)
    attn_mma_kernel<<<dim3(SEQ/128, 2*NHEADS), 256, SMEM_ATTN>>>(p_qkvb, p_o_hi, p_o_lo, 0);
    cudaEventRecord(e_attn0, 0);
    // attention chunk 1 (batches 2,3) — overlaps out-proj chunk 0 on s2
    attn_mma_kernel<<<dim3(SEQ/128, 2*NHEADS), 256, SMEM_ATTN>>>(p_qkvb, p_o_hi, p_o_lo, 2);

    // side stream: out-proj chunk 0 (rows [0, HALF)) — after attn0 (converts already ordered on s2)
    cudaStreamWaitEvent(s2, e_attn0, 0);
    gemm_bf16x3<2,3><<<dim3(DMODEL/BN, HALF/BM), 256, SMEM_G3, s2>>>(
        p_o_hi, p_o_lo, p_wout_hi, p_wout_lo, out_b, x,
        out, nullptr, nullptr, HALF, DMODEL, DMODEL);
    cudaEventRecord(e_out0, s2);

    // main: out-proj chunk 1 (rows [HALF, MROWS))
    cudaStreamWaitEvent(0, e_cvt_all, 0);
    gemm_bf16x3<2,3><<<dim3(DMODEL/BN, HALF/BM), 256, SMEM_G3>>>(
        p_o_hi + (size_t)HALF * DMODEL, p_o_lo + (size_t)HALF * DMODEL,
        p_wout_hi, p_wout_lo, out_b, x + (size_t)HALF * DMODEL,
        out + (size_t)HALF * DMODEL, nullptr, nullptr, HALF, DMODEL, DMODEL);

    // join: LN2 needs both out chunks
    cudaStreamWaitEvent(0, e_out0, 0);
    layernorm_split_kernel<true><<<MROWS, 256>>>(out, ln2_g, ln2_b, p_h_hi, p_h_lo);
    gemm_bf16x3<1,3><<<dim3(DFF/BN, MROWS/BM), 256, SMEM_G3>>>(
        p_h_hi, p_h_lo, p_wfc1_hi, p_wfc1_lo, fc1_b, nullptr,
        nullptr, p_h2_hi, p_h2_lo, MROWS, DFF, DMODEL);
    gemm_bf16x3<2,2><<<dim3(DMODEL/BN, MROWS/BM), 256, SMEM_G2>>>(
        p_h2_hi, p_h2_lo, p_wfc2_hi, nullptr, fc2_b, out,
        out, nullptr, nullptr, MROWS, DMODEL, DFF);
}

// round 16
// speedup vs baseline: 1.0059x; 1.0059x over previous
#include <cuda_runtime.h>
#include <cuda_bf16.h>
#include <cstdint>
#include <cstddef>

// ---------------- problem constants ----------------
#define BATCH 4
#define SEQ   2048
#define DMODEL 1024
#define NHEADS 16
#define HDIM   64
#define DFF    4096
#define MROWS  (BATCH*SEQ)          // 8192
#define LN_EPS 1e-5f

typedef __nv_bfloat16  bf16;
typedef __nv_bfloat162 bf162;

// ---------------- scratch (device globals; no allocations allowed) ----------
__device__ bf16  g_qkvb[(size_t)MROWS * 3 * DMODEL];
__device__ bf16  g_h_hi[(size_t)MROWS * DMODEL];
__device__ bf16  g_h_lo[(size_t)MROWS * DMODEL];
__device__ bf16  g_o_hi[(size_t)MROWS * DMODEL];
__device__ bf16  g_o_lo[(size_t)MROWS * DMODEL];
__device__ bf16  g_h2_hi[(size_t)MROWS * DFF];
__device__ bf16  g_h2_lo[(size_t)MROWS * DFF];
__device__ bf16  g_wqkv_hi[(size_t)3*DMODEL*DMODEL];
__device__ bf16  g_wout_hi[(size_t)DMODEL*DMODEL];
__device__ bf16  g_wout_lo[(size_t)DMODEL*DMODEL];
__device__ bf16  g_wfc1_hi[(size_t)DFF*DMODEL];
__device__ bf16  g_wfc1_lo[(size_t)DFF*DMODEL];
__device__ bf16  g_wfc2_hi[(size_t)DMODEL*DFF];

// ---------------- helpers ----------------
__device__ __forceinline__ float gelu_exact(float x) {
    return 0.5f * x * (1.0f + erff(x * 0.70710678118654752f));
}
__device__ __forceinline__ void split2(float v, bf16& h, bf16& l) {
    h = __float2bfloat16(v);
    l = __float2bfloat16(v - __bfloat162float(h));
}
__device__ __forceinline__ uint32_t pk2(float a, float b) {
    bf162 t = __floats2bfloat162_rn(a, b);
    return *(uint32_t*)&t;
}
__device__ __forceinline__ void cp16(void* dst_smem, const void* src_gmem) {
    unsigned s = (unsigned)__cvta_generic_to_shared(dst_smem);
    asm volatile("cp.async.cg.shared.global [%0], [%1], 16;" :: "r"(s), "l"(src_gmem) : "memory");
}
__device__ __forceinline__ void cp_commit() {
    asm volatile("cp.async.commit_group;" ::: "memory");
}
template<int N>
__device__ __forceinline__ void cp_wait() {
    asm volatile("cp.async.wait_group %0;" :: "n"(N) : "memory");
}
__device__ __forceinline__ void mma16816(float* c, const uint32_t* a, const uint32_t* b) {
    asm volatile(
        "mma.sync.aligned.m16n8k16.row.col.f32.bf16.bf16.f32 "
        "{%0,%1,%2,%3}, {%4,%5,%6,%7}, {%8,%9}, {%0,%1,%2,%3};"
        : "+f"(c[0]), "+f"(c[1]), "+f"(c[2]), "+f"(c[3])
        : "r"(a[0]), "r"(a[1]), "r"(a[2]), "r"(a[3]), "r"(b[0]), "r"(b[1]));
}
__device__ __forceinline__ void ldsm_x4(uint32_t& r0, uint32_t& r1, uint32_t& r2, uint32_t& r3,
                                        const void* p) {
    uint32_t a = (uint32_t)__cvta_generic_to_shared(p);
    asm volatile("ldmatrix.sync.aligned.m8n8.x4.shared.b16 {%0,%1,%2,%3}, [%4];"
                 : "=r"(r0), "=r"(r1), "=r"(r2), "=r"(r3) : "r"(a));
}
__device__ __forceinline__ void ldsm_x4_t(uint32_t& r0, uint32_t& r1, uint32_t& r2, uint32_t& r3,
                                          const void* p) {
    uint32_t a = (uint32_t)__cvta_generic_to_shared(p);
    asm volatile("ldmatrix.sync.aligned.m8n8.x4.trans.shared.b16 {%0,%1,%2,%3}, [%4];"
                 : "=r"(r0), "=r"(r1), "=r"(r2), "=r"(r3) : "r"(a));
}

// ---------------- weight split kernel (fp32 -> bf16 hi/lo) -----------------
__global__ __launch_bounds__(256) void split_kernel(
    const float* __restrict__ in, bf16* __restrict__ hi, bf16* __restrict__ lo)
{
    int i = blockIdx.x * blockDim.x + threadIdx.x;
    float4 v = ((const float4*)in)[i];
    bf16 h0,h1,h2,h3,l0,l1,l2,l3;
    split2(v.x,h0,l0); split2(v.y,h1,l1); split2(v.z,h2,l2); split2(v.w,h3,l3);
    bf162 ha; ha.x=h0; ha.y=h1;  bf162 hb; hb.x=h2; hb.y=h3;
    bf162 la; la.x=l0; la.y=l1;  bf162 lb; lb.x=l2; lb.y=l3;
    ((bf162*)hi)[2*i]   = ha; ((bf162*)hi)[2*i+1] = hb;
    ((bf162*)lo)[2*i]   = la; ((bf162*)lo)[2*i+1] = lb;
}
__global__ __launch_bounds__(256) void cvt_kernel(
    const float* __restrict__ in, bf16* __restrict__ hi)
{
    int i = blockIdx.x * blockDim.x + threadIdx.x;
    float4 v = ((const float4*)in)[i];
    uint2 o;
    o.x = pk2(v.x, v.y);
    o.y = pk2(v.z, v.w);
    ((uint2*)hi)[i] = o;
}

// ---------------- LayerNorm -> bf16 (hi, optional lo) ----------------------
template<bool WLO>
__global__ __launch_bounds__(256) void layernorm_split_kernel(
    const float* __restrict__ x, const float* __restrict__ g,
    const float* __restrict__ b, bf16* __restrict__ hi, bf16* __restrict__ lo)
{
    int row = blockIdx.x;
    const float4* xr = (const float4*)(x + (size_t)row * DMODEL);
    float4 v = xr[threadIdx.x];
    float s  = v.x + v.y + v.z + v.w;
    float sq = v.x*v.x + v.y*v.y + v.z*v.z + v.w*v.w;
    #pragma unroll
    for (int o = 16; o; o >>= 1) {
        s  += __shfl_xor_sync(0xffffffffu, s,  o);
        sq += __shfl_xor_sync(0xffffffffu, sq, o);
    }
    __shared__ float ss[8], ssq[8];
    int w = threadIdx.x >> 5, lane = threadIdx.x & 31;
    if (lane == 0) { ss[w] = s; ssq[w] = sq; }
    __syncthreads();
    float st = 0.f, sqt = 0.f;
    #pragma unroll
    for (int k = 0; k < 8; k++) { st += ss[k]; sqt += ssq[k]; }
    float mean = st * (1.0f / DMODEL);
    float var  = sqt * (1.0f / DMODEL) - mean * mean;
    float inv  = rsqrtf(var + LN_EPS);
    float4 gg = ((const float4*)g)[threadIdx.x];
    float4 bb = ((const float4*)b)[threadIdx.x];
    float o0 = (v.x - mean) * inv * gg.x + bb.x;
    float o1 = (v.y - mean) * inv * gg.y + bb.y;
    float o2 = (v.z - mean) * inv * gg.z + bb.z;
    float o3 = (v.w - mean) * inv * gg.w + bb.w;
    bf16 h0,h1,h2,h3,l0,l1,l2,l3;
    split2(o0,h0,l0); split2(o1,h1,l1); split2(o2,h2,l2); split2(o3,h3,l3);
    bf162 ha; ha.x=h0; ha.y=h1;  bf162 hb; hb.x=h2; hb.y=h3;
    bf162* hp = (bf162*)(hi + (size_t)row * DMODEL);
    hp[2*threadIdx.x] = ha; hp[2*threadIdx.x+1] = hb;
    if (WLO) {
        bf162 la; la.x=l0; la.y=l1;  bf162 lb; lb.x=l2; lb.y=l3;
        bf162* lp = (bf162*)(lo + (size_t)row * DMODEL);
        lp[2*threadIdx.x] = la; lp[2*threadIdx.x+1] = lb;
    }
}

// ---------------- bf16 split tensor-core GEMM (2-stage, ldmatrix) ----------
// MODE 1: gelu -> split bf16; MODE 2: fp32 bias+resid; MODE 3: bf16 out
// PASSES 3: Ah*Bh+Al*Bh+Ah*Bl (4 tiles/stage); 2: 3 tiles; 1: 2 tiles
#define BM 128
#define BN 128
#define BK 32
#define SSTRIDE 40
#define TILE_B  (BM * SSTRIDE * 2)

template<int MODE, int PASSES>
__global__ __launch_bounds__(256, 2) void gemm_bf16x3(
    const bf16* __restrict__ Ah, const bf16* __restrict__ Al,
    const bf16* __restrict__ Bh, const bf16* __restrict__ Bl,
    const float* __restrict__ bias, const float* __restrict__ R,
    float* __restrict__ C, bf16* __restrict__ Chi, bf16* __restrict__ Clo,
    int M, int N, int K)
{
    extern __shared__ char smem[];
    constexpr int NTILES = (PASSES == 3) ? 4 : ((PASSES == 2) ? 3 : 2);
    constexpr int STG_B  = NTILES * TILE_B;
    constexpr int SLOT_BH = (PASSES >= 2) ? 2 : 1;
    const int tid  = threadIdx.x;
    const int bm = blockIdx.y * BM, bn = blockIdx.x * BN;
    const int warp = tid >> 5, lane = tid & 31;
    const int wm = warp >> 2, wn = warp & 3;
    const int gg = lane >> 2, qt = lane & 3;
    const int g8 = lane >> 3, lr = lane & 7;

    const bf16* gmat0 = Ah + (size_t)bm * K;
    const bf16* gmat1 = (PASSES >= 2) ? (Al + (size_t)bm * K) : nullptr;
    const bf16* gmat2 = Bh + (size_t)bn * K;
    const bf16* gmat3 = (PASSES == 3) ? (Bl + (size_t)bn * K) : nullptr;

    float acc[4][4][4];
    #pragma unroll
    for (int i = 0; i < 4; i++)
        #pragma unroll
        for (int j = 0; j < 4; j++)
            #pragma unroll
            for (int q = 0; q < 4; q++) acc[i][j][q] = 0.f;

    const int NK = K / BK;

    auto issue = [&](int k0, int st) {
        char* sb = smem + st * STG_B;
        #pragma unroll
        for (int c = 0; c < 2; c++) {
            int chunk = tid + c * 256;
            int row = chunk >> 2, col = chunk & 3;
            size_t goff = (size_t)row * K + k0 + col * 8;
            char*  sdst = sb + row * (SSTRIDE * 2) + col * 16;
            cp16(sdst + 0 * TILE_B, gmat0 + goff);
            if (PASSES >= 2) cp16(sdst + 1 * TILE_B, gmat1 + goff);
            cp16(sdst + SLOT_BH * TILE_B, gmat2 + goff);
            if (PASSES == 3) cp16(sdst + 3 * TILE_B, gmat3 + goff);
        }
    };

    issue(0, 0); cp_commit();

    const int a_row = (g8 & 1) * 8 + lr;
    const int a_col = (g8 >> 1) * 8;
    const int b_row = (g8 >> 1) * 8 + lr;
    const int b_col = (g8 & 1) * 8;

    for (int ks = 0; ks < NK; ks++) {
        const int cur = ks & 1;
        if (ks + 1 < NK) { issue((ks + 1) * BK, cur ^ 1); cp_commit(); cp_wait<1>(); }
        else             { cp_wait<0>(); }
        __syncthreads();

        const bf16* sAh = (const bf16*)(smem + cur * STG_B);
        const bf16* sAl = sAh + BM * SSTRIDE;
        const bf16* sBh = sAh + SLOT_BH * BM * SSTRIDE;
        const bf16* sBl = sAh + 3 * BM * SSTRIDE;

        #pragma unroll
        for (int kk = 0; kk < BK; kk += 16) {
            uint32_t afr[4][4], bfr[4][2];
            #pragma unroll
            for (int mt = 0; mt < 4; mt++) {
                const bf16* p = sAh + (wm*64 + mt*16 + a_row) * SSTRIDE + kk + a_col;
                ldsm_x4(afr[mt][0], afr[mt][1], afr[mt][2], afr[mt][3], p);
            }
            #pragma unroll
            for (int np = 0; np < 2; np++) {
                const bf16* p = sBh + (wn*32 + np*16 + b_row) * SSTRIDE + kk + b_col;
                ldsm_x4(bfr[2*np][0], bfr[2*np][1], bfr[2*np+1][0], bfr[2*np+1][1], p);
            }
            #pragma unroll
            for (int mt = 0; mt < 4; mt++)
                #pragma unroll
                for (int nt = 0; nt < 4; nt++)
                    mma16816(acc[mt][nt], afr[mt], bfr[nt]);
            if (PASSES >= 2) {
                uint32_t afl[4][4];
                #pragma unroll
                for (int mt = 0; mt < 4; mt++) {
                    const bf16* p = sAl + (wm*64 + mt*16 + a_row) * SSTRIDE + kk + a_col;
                    ldsm_x4(afl[mt][0], afl[mt][1], afl[mt][2], afl[mt][3], p);
                }
                #pragma unroll
                for (int mt = 0; mt < 4; mt++)
                    #pragma unroll
                    for (int nt = 0; nt < 4; nt++)
                        mma16816(acc[mt][nt], afl[mt], bfr[nt]);
            }
            if (PASSES == 3) {
                #pragma unroll
                for (int np = 0; np < 2; np++) {
                    const bf16* p = sBl + (wn*32 + np*16 + b_row) * SSTRIDE + kk + b_col;
                    ldsm_x4(bfr[2*np][0], bfr[2*np][1], bfr[2*np+1][0], bfr[2*np+1][1], p);
                }
                #pragma unroll
                for (int mt = 0; mt < 4; mt++)
                    #pragma unroll
                    for (int nt = 0; nt < 4; nt++)
                        mma16816(acc[mt][nt], afr[mt], bfr[nt]);
            }
        }
        __syncthreads();
    }

    #pragma unroll
    for (int mt = 0; mt < 4; mt++) {
        #pragma unroll
        for (int nt = 0; nt < 4; nt++) {
            int r  = bm + wm * 64 + mt * 16 + gg;
            int c0 = bn + wn * 32 + nt * 8 + 2 * qt;
            float2 bv = *(const float2*)(bias + c0);
            float v00 = acc[mt][nt][0] + bv.x;
            float v01 = acc[mt][nt][1] + bv.y;
            float v10 = acc[mt][nt][2] + bv.x;
            float v11 = acc[mt][nt][3] + bv.y;
            if (MODE == 2) {
                float2 r0 = *(const float2*)(R + (size_t)r * N + c0);
                float2 r1 = *(const float2*)(R + (size_t)(r + 8) * N + c0);
                v00 += r0.x; v01 += r0.y; v10 += r1.x; v11 += r1.y;
            }
            if (MODE == 1) {
                v00 = gelu_exact(v00); v01 = gelu_exact(v01);
                v10 = gelu_exact(v10); v11 = gelu_exact(v11);
                bf16 h0,h1,h2,h3,l0,l1,l2,l3;
                split2(v00,h0,l0); split2(v01,h1,l1);
                split2(v10,h2,l2); split2(v11,h3,l3);
                bf162 pa; pa.x=h0; pa.y=h1;  bf162 pb; pb.x=h2; pb.y=h3;
                bf162 qa; qa.x=l0; qa.y=l1;  bf162 qb; qb.x=l2; qb.y=l3;
                *(bf162*)(Chi + (size_t)r * N + c0)       = pa;
                *(bf162*)(Chi + (size_t)(r + 8) * N + c0) = pb;
                *(bf162*)(Clo + (size_t)r * N + c0)       = qa;
                *(bf162*)(Clo + (size_t)(r + 8) * N + c0) = qb;
            } else if (MODE == 3) {
                uint32_t pa = pk2(v00, v01);
                uint32_t pb = pk2(v10, v11);
                *(uint32_t*)(Chi + (size_t)r * N + c0)       = pa;
                *(uint32_t*)(Chi + (size_t)(r + 8) * N + c0) = pb;
            } else {
                *(float2*)(C + (size_t)r * N + c0)       = make_float2(v00, v01);
                *(float2*)(C + (size_t)(r + 8) * N + c0) = make_float2(v10, v11);
            }
        }
    }
}

// ---------------- tensor-core causal flash attention ------------------------
#define KSTR 72

__global__ __launch_bounds__(256) void attn_mma_kernel(
    const bf16* __restrict__ qkvb, bf16* __restrict__ o_hi, bf16* __restrict__ o_lo)
{
    extern __shared__ char asmem[];
    bf16* Qs = (bf16*)asmem;
    bf16* Ks = Qs + 128 * KSTR;
    bf16* Vs = Ks + 2 * 64 * KSTR;

    const int tid = threadIdx.x;
    const int warp = tid >> 5, lane = tid & 31;
    const int gg = lane >> 2, qt = lane & 3;
    const int g8 = lane >> 3, lr = lane & 7;
    const int qt_blk = gridDim.x - 1 - blockIdx.x;      // heavy-first
    const int bh = blockIdx.y;
    const int b = bh >> 4, h = bh & 15;
    const int q0 = qt_blk * 128;
    const size_t ROW = 3 * DMODEL;
    const bf16* qg = qkvb + (size_t)(b * SEQ) * ROW + h * HDIM;
    const bf16* kg = qg + DMODEL;
    const bf16* vg = qg + 2 * DMODEL;

    #pragma unroll
    for (int u = 0; u < 4; u++) {
        int idx = tid + u * 256;
        int r = idx >> 3, c = (idx & 7) * 8;
        *(uint4*)&Qs[r * KSTR + c] = *(const uint4*)(qg + (size_t)(q0 + r) * ROW + c);
    }
    __syncthreads();

    uint32_t qf[4][4];
    {
        const bf162 sc = __floats2bfloat162_rn(0.125f, 0.125f);
        #pragma unroll
        for (int kt = 0; kt < 4; kt++) {
            const bf16* p = &Qs[(warp * 16 + (g8 & 1) * 8 + lr) * KSTR + kt * 16 + (g8 >> 1) * 8];
            ldsm_x4(qf[kt][0], qf[kt][1], qf[kt][2], qf[kt][3], p);
            #pragma unroll
            for (int i = 0; i < 4; i++) {
                bf162 v = *(bf162*)&qf[kt][i];
                v = __hmul2(v, sc);
                qf[kt][i] = *(uint32_t*)&v;
            }
        }
    }

    float oacc[8][4];
    #pragma unroll
    for (int nt = 0; nt < 8; nt++)
        #pragma unroll
        for (int i = 0; i < 4; i++) oacc[nt][i] = 0.f;
    float m0 = -1e30f, m1 = -1e30f, l0 = 0.f, l1 = 0.f;

    const int ntiles = qt_blk * 2 + 2;
    const int wbase = q0 + warp * 16;
    const int wmax  = wbase + 15;

    auto issue = [&](int t, int st) {
        #pragma unroll
        for (int u = 0; u < 2; u++) {
            int idx = tid + u * 256;
            int r = idx >> 3, c = (idx & 7) * 8;
            size_t goff = (size_t)(t * 64 + r) * ROW + c;
            cp16(&Ks[st * 64 * KSTR + r * KSTR + c], kg + goff);
            cp16(&Vs[st * 64 * KSTR + r * KSTR + c], vg + goff);
        }
    };

    issue(0, 0); cp_commit();

    for (int t = 0; t < ntiles; t++) {
        const int cur = t & 1;
        if (t + 1 < ntiles) { issue(t + 1, cur ^ 1); cp_commit(); cp_wait<1>(); }
        else                { cp_wait<0>(); }
        __syncthreads();

        const int j0 = t * 64;
        if (j0 <= wmax) {
            const bf16* Kt = &Ks[cur * 64 * KSTR];
            const bf16* Vt = &Vs[cur * 64 * KSTR];

            float sacc[8][4];
            #pragma unroll
            for (int nt = 0; nt < 8; nt++)
                #pragma unroll
                for (int i = 0; i < 4; i++) sacc[nt][i] = 0.f;

            #pragma unroll
            for (int kt = 0; kt < 4; kt++) {
                uint32_t bfr[8][2];
                #pragma unroll
                for (int np = 0; np < 4; np++) {
                    const bf16* p = &Kt[(np * 16 + (g8 >> 1) * 8 + lr) * KSTR + kt * 16 + (g8 & 1) * 8];
                    ldsm_x4(bfr[2*np][0], bfr[2*np][1], bfr[2*np+1][0], bfr[2*np+1][1], p);
                }
                #pragma unroll
                for (int nt = 0; nt < 8; nt++)
                    mma16816(sacc[nt], qf[kt], bfr[nt]);
            }

            const int r0 = wbase + gg, r1 = r0 + 8;
            if (j0 + 63 > wbase) {
                #pragma unroll
                for (int nt = 0; nt < 8; nt++) {
                    int c0 = j0 + nt * 8 + 2 * qt, c1 = c0 + 1;
                    if (c0 > r0) sacc[nt][0] = -1e30f;
                    if (c1 > r0) sacc[nt][1] = -1e30f;
                    if (c0 > r1) sacc[nt][2] = -1e30f;
                    if (c1 > r1) sacc[nt][3] = -1e30f;
                }
            }

            float mx0 = -1e30f, mx1 = -1e30f;
            #pragma unroll
            for (int nt = 0; nt < 8; nt++) {
                mx0 = fmaxf(mx0, fmaxf(sacc[nt][0], sacc[nt][1]));
                mx1 = fmaxf(mx1, fmaxf(sacc[nt][2], sacc[nt][3]));
            }
            mx0 = fmaxf(mx0, __shfl_xor_sync(0xffffffffu, mx0, 1));
            mx0 = fmaxf(mx0, __shfl_xor_sync(0xffffffffu, mx0, 2));
            mx1 = fmaxf(mx1, __shfl_xor_sync(0xffffffffu, mx1, 1));
            mx1 = fmaxf(mx1, __shfl_xor_sync(0xffffffffu, mx1, 2));
            float mn0 = fmaxf(m0, mx0), mn1 = fmaxf(m1, mx1);
            float cr0 = __expf(m0 - mn0), cr1 = __expf(m1 - mn1);
            m0 = mn0; m1 = mn1;

            float ps0 = 0.f, ps1 = 0.f;
            uint32_t pa[4][4];
            #pragma unroll
            for (int np = 0; np < 4; np++) {
                float e00 = __expf(sacc[2*np  ][0] - mn0);
                float e01 = __expf(sacc[2*np  ][1] - mn0);
                float e02 = __expf(sacc[2*np  ][2] - mn1);
                float e03 = __expf(sacc[2*np  ][3] - mn1);
                float e10 = __expf(sacc[2*np+1][0] - mn0);
                float e11 = __expf(sacc[2*np+1][1] - mn0);
                float e12 = __expf(sacc[2*np+1][2] - mn1);
                float e13 = __expf(sacc[2*np+1][3] - mn1);
                ps0 += e00 + e01 + e10 + e11;
                ps1 += e02 + e03 + e12 + e13;
                pa[np][0] = pk2(e00, e01);
                pa[np][1] = pk2(e02, e03);
                pa[np][2] = pk2(e10, e11);
                pa[np][3] = pk2(e12, e13);
            }
            ps0 += __shfl_xor_sync(0xffffffffu, ps0, 1);
            ps0 += __shfl_xor_sync(0xffffffffu, ps0, 2);
            ps1 += __shfl_xor_sync(0xffffffffu, ps1, 1);
            ps1 += __shfl_xor_sync(0xffffffffu, ps1, 2);
            l0 = l0 * cr0 + ps0;
            l1 = l1 * cr1 + ps1;
            #pragma unroll
            for (int nt = 0; nt < 8; nt++) {
                oacc[nt][0] *= cr0; oacc[nt][1] *= cr0;
                oacc[nt][2] *= cr1; oacc[nt][3] *= cr1;
            }

            #pragma unroll
            for (int kt = 0; kt < 4; kt++) {
                uint32_t vfr[8][2];
                #pragma unroll
                for (int np = 0; np < 4; np++) {
                    const bf16* p = &Vt[(kt * 16 + (g8 & 1) * 8 + lr) * KSTR + np * 16 + (g8 >> 1) * 8];
                    ldsm_x4_t(vfr[2*np][0], vfr[2*np][1], vfr[2*np+1][0], vfr[2*np+1][1], p);
                }
                #pragma unroll
                for (int nt = 0; nt < 8; nt++)
                    mma16816(oacc[nt], pa[kt], vfr[nt]);
            }
        }
        __syncthreads();
    }

    float inv0 = 1.f / l0, inv1 = 1.f / l1;
    int grow0 = b * SEQ + wbase + gg;
    int grow1 = grow0 + 8;
    #pragma unroll
    for (int nt = 0; nt < 8; nt++) {
        int col = h * HDIM + nt * 8 + 2 * qt;
        float v00 = oacc[nt][0] * inv0, v01 = oacc[nt][1] * inv0;
        float v10 = oacc[nt][2] * inv1, v11 = oacc[nt][3] * inv1;
        bf16 h0,h1,h2,h3,l0b,l1b,l2b,l3b;
        split2(v00,h0,l0b); split2(v01,h1,l1b);
        split2(v10,h2,l2b); split2(v11,h3,l3b);
        bf162 pa; pa.x=h0; pa.y=h1;  bf162 pb; pb.x=h2; pb.y=h3;
        bf162 qa; qa.x=l0b; qa.y=l1b; bf162 qb; qb.x=l2b; qb.y=l3b;
        *(bf162*)(o_hi + (size_t)grow0 * DMODEL + col) = pa;
        *(bf162*)(o_hi + (size_t)grow1 * DMODEL + col) = pb;
        *(bf162*)(o_lo + (size_t)grow0 * DMODEL + col) = qa;
        *(bf162*)(o_lo + (size_t)grow1 * DMODEL + col) = qb;
    }
}

// ---------------- launch ----------------
extern "C" void kernel_launch(void* const* d_in, const int* in_sizes, int n_in,
                              void* d_out, int out_size)
{
    const float* x     = (const float*)d_in[0];
    const float* ln1_g = (const float*)d_in[1];
    const float* ln1_b = (const float*)d_in[2];
    const float* qkv_w = (const float*)d_in[3];
    const float* qkv_b = (const float*)d_in[4];
    const float* out_w = (const float*)d_in[5];
    const float* out_b = (const float*)d_in[6];
    const float* ln2_g = (const float*)d_in[7];
    const float* ln2_b = (const float*)d_in[8];
    const float* fc1_w = (const float*)d_in[9];
    const float* fc1_b = (const float*)d_in[10];
    const float* fc2_w = (const float*)d_in[11];
    const float* fc2_b = (const float*)d_in[12];
    float* out = (float*)d_out;

    static bf16 *p_qkvb = nullptr;
    static bf16 *p_h_hi, *p_h_lo, *p_o_hi, *p_o_lo, *p_h2_hi, *p_h2_lo;
    static bf16 *p_wqkv_hi, *p_wout_hi, *p_wout_lo;
    static bf16 *p_wfc1_hi, *p_wfc1_lo, *p_wfc2_hi;
    static cudaStream_t s2 = nullptr;
    static cudaEvent_t e0, e_cvtq, e_cvt_all;
    if (!p_qkvb) {
        cudaGetSymbolAddress((void**)&p_qkvb,   g_qkvb);
        cudaGetSymbolAddress((void**)&p_h_hi,   g_h_hi);
        cudaGetSymbolAddress((void**)&p_h_lo,   g_h_lo);
        cudaGetSymbolAddress((void**)&p_o_hi,   g_o_hi);
        cudaGetSymbolAddress((void**)&p_o_lo,   g_o_lo);
        cudaGetSymbolAddress((void**)&p_h2_hi,  g_h2_hi);
        cudaGetSymbolAddress((void**)&p_h2_lo,  g_h2_lo);
        cudaGetSymbolAddress((void**)&p_wqkv_hi, g_wqkv_hi);
        cudaGetSymbolAddress((void**)&p_wout_hi, g_wout_hi);
        cudaGetSymbolAddress((void**)&p_wout_lo, g_wout_lo);
        cudaGetSymbolAddress((void**)&p_wfc1_hi, g_wfc1_hi);
        cudaGetSymbolAddress((void**)&p_wfc1_lo, g_wfc1_lo);
        cudaGetSymbolAddress((void**)&p_wfc2_hi, g_wfc2_hi);
        cudaStreamCreateWithFlags(&s2, cudaStreamNonBlocking);
        cudaEventCreateWithFlags(&e0,        cudaEventDisableTiming);
        cudaEventCreateWithFlags(&e_cvtq,    cudaEventDisableTiming);
        cudaEventCreateWithFlags(&e_cvt_all, cudaEventDisableTiming);
    }

    const int SMEM_G3 = 2 * (4 * TILE_B);                 // 81920
    const int SMEM_G2 = 2 * (3 * TILE_B);                 // 61440
    const int SMEM_G1 = 2 * (2 * TILE_B);                 // 40960
    const int SMEM_ATTN = (128 + 2*64 + 2*64) * KSTR * 2; // 55296
    cudaFuncSetAttribute((const void*)gemm_bf16x3<1,3>, cudaFuncAttributeMaxDynamicSharedMemorySize, SMEM_G3);
    cudaFuncSetAttribute((const void*)gemm_bf16x3<2,3>, cudaFuncAttributeMaxDynamicSharedMemorySize, SMEM_G3);
    cudaFuncSetAttribute((const void*)gemm_bf16x3<2,2>, cudaFuncAttributeMaxDynamicSharedMemorySize, SMEM_G2);
    cudaFuncSetAttribute((const void*)gemm_bf16x3<3,1>, cudaFuncAttributeMaxDynamicSharedMemorySize, SMEM_G1);
    cudaFuncSetAttribute((const void*)attn_mma_kernel,  cudaFuncAttributeMaxDynamicSharedMemorySize, SMEM_ATTN);

    // ---- fork: weight converts on side stream (off the critical path) ----
    cudaEventRecord(e0, 0);
    cudaStreamWaitEvent(s2, e0, 0);
    cvt_kernel<<<(3*DMODEL*DMODEL)/4/256, 256, 0, s2>>>(qkv_w, p_wqkv_hi);
    cudaEventRecord(e_cvtq, s2);
    split_kernel<<<(DMODEL*DMODEL)/4/256, 256, 0, s2>>>(out_w, p_wout_hi, p_wout_lo);
    split_kernel<<<(DFF*DMODEL)/4/256,    256, 0, s2>>>(fc1_w, p_wfc1_hi, p_wfc1_lo);
    cvt_kernel  <<<(DMODEL*DFF)/4/256,    256, 0, s2>>>(fc2_w, p_wfc2_hi);
    cudaEventRecord(e_cvt_all, s2);

    // ---- main stream: critical path ----
    layernorm_split_kernel<false><<<MROWS, 256>>>(x, ln1_g, ln1_b, p_h_hi, nullptr);
    cudaStreamWaitEvent(0, e_cvtq, 0);
    gemm_bf16x3<3,1><<<dim3(3*DMODEL/BN, MROWS/BM), 256, SMEM_G1>>>(
        p_h_hi, nullptr, p_wqkv_hi, nullptr, qkv_b, nullptr,
        nullptr, p_qkvb, nullptr, MROWS, 3*DMODEL, DMODEL);
    attn_mma_kernel<<<dim3(SEQ/128, BATCH*NHEADS), 256, SMEM_ATTN>>>(p_qkvb, p_o_hi, p_o_lo);
    cudaStreamWaitEvent(0, e_cvt_all, 0);
    gemm_bf16x3<2,3><<<dim3(DMODEL/BN, MROWS/BM), 256, SMEM_G3>>>(
        p_o_hi, p_o_lo, p_wout_hi, p_wout_lo, out_b, x,
        out, nullptr, nullptr, MROWS, DMODEL, DMODEL);
    layernorm_split_kernel<true><<<MROWS, 256>>>(out, ln2_g, ln2_b, p_h_hi, p_h_lo);
    gemm_bf16x3<1,3><<<dim3(DFF/BN, MROWS/BM), 256, SMEM_G3>>>(
        p_h_hi, p_h_lo, p_wfc1_hi, p_wfc1_lo, fc1_b, nullptr,
        nullptr, p_h2_hi, p_h2_lo, MROWS, DFF, DMODEL);
    gemm_bf16x3<2,2><<<dim3(DMODEL/BN, MROWS/BM), 256, SMEM_G2>>>(
        p_h2_hi, p_h2_lo, p_wfc2_hi, nullptr, fc2_b, out,
        out, nullptr, nullptr, MROWS, DMODEL, DFF);
}

// round 17
// speedup vs baseline: 1.0092x; 1.0033x over previous
#include <cuda_runtime.h>
#include <cuda_bf16.h>
#include <cstdint>
#include <cstddef>

// ---------------- problem constants ----------------
#define BATCH 4
#define SEQ   2048
#define DMODEL 1024
#define NHEADS 16
#define HDIM   64
#define DFF    4096
#define MROWS  (BATCH*SEQ)          // 8192
#define LN_EPS 1e-5f

typedef __nv_bfloat16  bf16;
typedef __nv_bfloat162 bf162;

// ---------------- scratch (device globals; no allocations allowed) ----------
__device__ bf16  g_qkvb[(size_t)MROWS * 3 * DMODEL];
__device__ bf16  g_h_hi[(size_t)MROWS * DMODEL];
__device__ bf16  g_h_lo[(size_t)MROWS * DMODEL];
__device__ bf16  g_o_hi[(size_t)MROWS * DMODEL];
__device__ bf16  g_o_lo[(size_t)MROWS * DMODEL];
__device__ bf16  g_h2_hi[(size_t)MROWS * DFF];
__device__ bf16  g_h2_lo[(size_t)MROWS * DFF];
__device__ bf16  g_wqkv_hi[(size_t)3*DMODEL*DMODEL];
__device__ bf16  g_wout_hi[(size_t)DMODEL*DMODEL];
__device__ bf16  g_wout_lo[(size_t)DMODEL*DMODEL];
__device__ bf16  g_wfc1_hi[(size_t)DFF*DMODEL];
__device__ bf16  g_wfc1_lo[(size_t)DFF*DMODEL];
__device__ bf16  g_wfc2_hi[(size_t)DMODEL*DFF];

// ---------------- helpers ----------------
__device__ __forceinline__ float gelu_exact(float x) {
    return 0.5f * x * (1.0f + erff(x * 0.70710678118654752f));
}
__device__ __forceinline__ void split2(float v, bf16& h, bf16& l) {
    h = __float2bfloat16(v);
    l = __float2bfloat16(v - __bfloat162float(h));
}
__device__ __forceinline__ uint32_t pk2(float a, float b) {
    bf162 t = __floats2bfloat162_rn(a, b);
    return *(uint32_t*)&t;
}
__device__ __forceinline__ void cp16(void* dst_smem, const void* src_gmem) {
    unsigned s = (unsigned)__cvta_generic_to_shared(dst_smem);
    asm volatile("cp.async.cg.shared.global [%0], [%1], 16;" :: "r"(s), "l"(src_gmem) : "memory");
}
__device__ __forceinline__ void cp_commit() {
    asm volatile("cp.async.commit_group;" ::: "memory");
}
template<int N>
__device__ __forceinline__ void cp_wait() {
    asm volatile("cp.async.wait_group %0;" :: "n"(N) : "memory");
}
__device__ __forceinline__ void mma16816(float* c, const uint32_t* a, const uint32_t* b) {
    asm volatile(
        "mma.sync.aligned.m16n8k16.row.col.f32.bf16.bf16.f32 "
        "{%0,%1,%2,%3}, {%4,%5,%6,%7}, {%8,%9}, {%0,%1,%2,%3};"
        : "+f"(c[0]), "+f"(c[1]), "+f"(c[2]), "+f"(c[3])
        : "r"(a[0]), "r"(a[1]), "r"(a[2]), "r"(a[3]), "r"(b[0]), "r"(b[1]));
}
__device__ __forceinline__ void ldsm_x4(uint32_t& r0, uint32_t& r1, uint32_t& r2, uint32_t& r3,
                                        const void* p) {
    uint32_t a = (uint32_t)__cvta_generic_to_shared(p);
    asm volatile("ldmatrix.sync.aligned.m8n8.x4.shared.b16 {%0,%1,%2,%3}, [%4];"
                 : "=r"(r0), "=r"(r1), "=r"(r2), "=r"(r3) : "r"(a));
}
__device__ __forceinline__ void ldsm_x4_t(uint32_t& r0, uint32_t& r1, uint32_t& r2, uint32_t& r3,
                                          const void* p) {
    uint32_t a = (uint32_t)__cvta_generic_to_shared(p);
    asm volatile("ldmatrix.sync.aligned.m8n8.x4.trans.shared.b16 {%0,%1,%2,%3}, [%4];"
                 : "=r"(r0), "=r"(r1), "=r"(r2), "=r"(r3) : "r"(a));
}

// ---------------- weight split kernel (fp32 -> bf16 hi/lo) -----------------
__global__ __launch_bounds__(256) void split_kernel(
    const float* __restrict__ in, bf16* __restrict__ hi, bf16* __restrict__ lo)
{
    int i = blockIdx.x * blockDim.x + threadIdx.x;
    float4 v = ((const float4*)in)[i];
    bf16 h0,h1,h2,h3,l0,l1,l2,l3;
    split2(v.x,h0,l0); split2(v.y,h1,l1); split2(v.z,h2,l2); split2(v.w,h3,l3);
    bf162 ha; ha.x=h0; ha.y=h1;  bf162 hb; hb.x=h2; hb.y=h3;
    bf162 la; la.x=l0; la.y=l1;  bf162 lb; lb.x=l2; lb.y=l3;
    ((bf162*)hi)[2*i]   = ha; ((bf162*)hi)[2*i+1] = hb;
    ((bf162*)lo)[2*i]   = la; ((bf162*)lo)[2*i+1] = lb;
}
__global__ __launch_bounds__(256) void cvt_kernel(
    const float* __restrict__ in, bf16* __restrict__ hi)
{
    int i = blockIdx.x * blockDim.x + threadIdx.x;
    float4 v = ((const float4*)in)[i];
    uint2 o;
    o.x = pk2(v.x, v.y);
    o.y = pk2(v.z, v.w);
    ((uint2*)hi)[i] = o;
}

// ---------------- LayerNorm (2 rows/block) -> bf16 (hi, optional lo) -------
// 256 threads: threads [0,128) handle row 2*blk, [128,256) row 2*blk+1.
// Each thread loads 2 float4 (32B). 4-warp cross-reduce per row via smem.
template<bool WLO>
__global__ __launch_bounds__(256) void layernorm_split_kernel(
    const float* __restrict__ x, const float* __restrict__ g,
    const float* __restrict__ b, bf16* __restrict__ hi, bf16* __restrict__ lo)
{
    const int tid = threadIdx.x;
    const int rid = tid >> 7;            // 0 or 1
    const int tix = tid & 127;           // 0..127
    const int row = blockIdx.x * 2 + rid;
    const float4* xr = (const float4*)(x + (size_t)row * DMODEL);
    float4 v0 = xr[tix];
    float4 v1 = xr[tix + 128];
    float s  = v0.x + v0.y + v0.z + v0.w + v1.x + v1.y + v1.z + v1.w;
    float sq = v0.x*v0.x + v0.y*v0.y + v0.z*v0.z + v0.w*v0.w
             + v1.x*v1.x + v1.y*v1.y + v1.z*v1.z + v1.w*v1.w;
    #pragma unroll
    for (int o = 16; o; o >>= 1) {
        s  += __shfl_xor_sync(0xffffffffu, s,  o);
        sq += __shfl_xor_sync(0xffffffffu, sq, o);
    }
    __shared__ float ss[8], ssq[8];
    int w = tid >> 5, lane = tid & 31;
    if (lane == 0) { ss[w] = s; ssq[w] = sq; }
    __syncthreads();
    float st = 0.f, sqt = 0.f;
    const int base = rid * 4;
    #pragma unroll
    for (int k = 0; k < 4; k++) { st += ss[base + k]; sqt += ssq[base + k]; }
    float mean = st * (1.0f / DMODEL);
    float var  = sqt * (1.0f / DMODEL) - mean * mean;
    float inv  = rsqrtf(var + LN_EPS);

    bf162* hp = (bf162*)(hi + (size_t)row * DMODEL);
    bf162* lp = WLO ? (bf162*)(lo + (size_t)row * DMODEL) : nullptr;
    #pragma unroll
    for (int half = 0; half < 2; half++) {
        const int ci = tix + half * 128;           // float4 index in row
        float4 vv = half ? v1 : v0;
        float4 gg = ((const float4*)g)[ci];
        float4 bb = ((const float4*)b)[ci];
        float o0 = (vv.x - mean) * inv * gg.x + bb.x;
        float o1 = (vv.y - mean) * inv * gg.y + bb.y;
        float o2 = (vv.z - mean) * inv * gg.z + bb.z;
        float o3 = (vv.w - mean) * inv * gg.w + bb.w;
        bf16 h0,h1,h2,h3,l0,l1,l2,l3;
        split2(o0,h0,l0); split2(o1,h1,l1); split2(o2,h2,l2); split2(o3,h3,l3);
        bf162 ha; ha.x=h0; ha.y=h1;  bf162 hb; hb.x=h2; hb.y=h3;
        hp[2*ci] = ha; hp[2*ci+1] = hb;
        if (WLO) {
            bf162 la; la.x=l0; la.y=l1;  bf162 lb; lb.x=l2; lb.y=l3;
            lp[2*ci] = la; lp[2*ci+1] = lb;
        }
    }
}

// ---------------- bf16 split tensor-core GEMM (2-stage, ldmatrix) ----------
// MODE 1: gelu -> split bf16; MODE 2: fp32 bias+resid; MODE 3: bf16 out
// PASSES 3: Ah*Bh+Al*Bh+Ah*Bl (4 tiles/stage); 2: 3 tiles; 1: 2 tiles
#define BM 128
#define BN 128
#define BK 32
#define SSTRIDE 40
#define TILE_B  (BM * SSTRIDE * 2)

template<int MODE, int PASSES>
__global__ __launch_bounds__(256, 2) void gemm_bf16x3(
    const bf16* __restrict__ Ah, const bf16* __restrict__ Al,
    const bf16* __restrict__ Bh, const bf16* __restrict__ Bl,
    const float* __restrict__ bias, const float* __restrict__ R,
    float* __restrict__ C, bf16* __restrict__ Chi, bf16* __restrict__ Clo,
    int M, int N, int K)
{
    extern __shared__ char smem[];
    constexpr int NTILES = (PASSES == 3) ? 4 : ((PASSES == 2) ? 3 : 2);
    constexpr int STG_B  = NTILES * TILE_B;
    constexpr int SLOT_BH = (PASSES >= 2) ? 2 : 1;
    const int tid  = threadIdx.x;
    const int bm = blockIdx.y * BM, bn = blockIdx.x * BN;
    const int warp = tid >> 5, lane = tid & 31;
    const int wm = warp >> 2, wn = warp & 3;
    const int gg = lane >> 2, qt = lane & 3;
    const int g8 = lane >> 3, lr = lane & 7;

    const bf16* gmat0 = Ah + (size_t)bm * K;
    const bf16* gmat1 = (PASSES >= 2) ? (Al + (size_t)bm * K) : nullptr;
    const bf16* gmat2 = Bh + (size_t)bn * K;
    const bf16* gmat3 = (PASSES == 3) ? (Bl + (size_t)bn * K) : nullptr;

    float acc[4][4][4];
    #pragma unroll
    for (int i = 0; i < 4; i++)
        #pragma unroll
        for (int j = 0; j < 4; j++)
            #pragma unroll
            for (int q = 0; q < 4; q++) acc[i][j][q] = 0.f;

    const int NK = K / BK;

    auto issue = [&](int k0, int st) {
        char* sb = smem + st * STG_B;
        #pragma unroll
        for (int c = 0; c < 2; c++) {
            int chunk = tid + c * 256;
            int row = chunk >> 2, col = chunk & 3;
            size_t goff = (size_t)row * K + k0 + col * 8;
            char*  sdst = sb + row * (SSTRIDE * 2) + col * 16;
            cp16(sdst + 0 * TILE_B, gmat0 + goff);
            if (PASSES >= 2) cp16(sdst + 1 * TILE_B, gmat1 + goff);
            cp16(sdst + SLOT_BH * TILE_B, gmat2 + goff);
            if (PASSES == 3) cp16(sdst + 3 * TILE_B, gmat3 + goff);
        }
    };

    issue(0, 0); cp_commit();

    const int a_row = (g8 & 1) * 8 + lr;
    const int a_col = (g8 >> 1) * 8;
    const int b_row = (g8 >> 1) * 8 + lr;
    const int b_col = (g8 & 1) * 8;

    for (int ks = 0; ks < NK; ks++) {
        const int cur = ks & 1;
        if (ks + 1 < NK) { issue((ks + 1) * BK, cur ^ 1); cp_commit(); cp_wait<1>(); }
        else             { cp_wait<0>(); }
        __syncthreads();

        const bf16* sAh = (const bf16*)(smem + cur * STG_B);
        const bf16* sAl = sAh + BM * SSTRIDE;
        const bf16* sBh = sAh + SLOT_BH * BM * SSTRIDE;
        const bf16* sBl = sAh + 3 * BM * SSTRIDE;

        #pragma unroll
        for (int kk = 0; kk < BK; kk += 16) {
            uint32_t afr[4][4], bfr[4][2];
            #pragma unroll
            for (int mt = 0; mt < 4; mt++) {
                const bf16* p = sAh + (wm*64 + mt*16 + a_row) * SSTRIDE + kk + a_col;
                ldsm_x4(afr[mt][0], afr[mt][1], afr[mt][2], afr[mt][3], p);
            }
            #pragma unroll
            for (int np = 0; np < 2; np++) {
                const bf16* p = sBh + (wn*32 + np*16 + b_row) * SSTRIDE + kk + b_col;
                ldsm_x4(bfr[2*np][0], bfr[2*np][1], bfr[2*np+1][0], bfr[2*np+1][1], p);
            }
            #pragma unroll
            for (int mt = 0; mt < 4; mt++)
                #pragma unroll
                for (int nt = 0; nt < 4; nt++)
                    mma16816(acc[mt][nt], afr[mt], bfr[nt]);
            if (PASSES >= 2) {
                uint32_t afl[4][4];
                #pragma unroll
                for (int mt = 0; mt < 4; mt++) {
                    const bf16* p = sAl + (wm*64 + mt*16 + a_row) * SSTRIDE + kk + a_col;
                    ldsm_x4(afl[mt][0], afl[mt][1], afl[mt][2], afl[mt][3], p);
                }
                #pragma unroll
                for (int mt = 0; mt < 4; mt++)
                    #pragma unroll
                    for (int nt = 0; nt < 4; nt++)
                        mma16816(acc[mt][nt], afl[mt], bfr[nt]);
            }
            if (PASSES == 3) {
                #pragma unroll
                for (int np = 0; np < 2; np++) {
                    const bf16* p = sBl + (wn*32 + np*16 + b_row) * SSTRIDE + kk + b_col;
                    ldsm_x4(bfr[2*np][0], bfr[2*np][1], bfr[2*np+1][0], bfr[2*np+1][1], p);
                }
                #pragma unroll
                for (int mt = 0; mt < 4; mt++)
                    #pragma unroll
                    for (int nt = 0; nt < 4; nt++)
                        mma16816(acc[mt][nt], afr[mt], bfr[nt]);
            }
        }
        __syncthreads();
    }

    #pragma unroll
    for (int mt = 0; mt < 4; mt++) {
        #pragma unroll
        for (int nt = 0; nt < 4; nt++) {
            int r  = bm + wm * 64 + mt * 16 + gg;
            int c0 = bn + wn * 32 + nt * 8 + 2 * qt;
            float2 bv = *(const float2*)(bias + c0);
            float v00 = acc[mt][nt][0] + bv.x;
            float v01 = acc[mt][nt][1] + bv.y;
            float v10 = acc[mt][nt][2] + bv.x;
            float v11 = acc[mt][nt][3] + bv.y;
            if (MODE == 2) {
                float2 r0 = *(const float2*)(R + (size_t)r * N + c0);
                float2 r1 = *(const float2*)(R + (size_t)(r + 8) * N + c0);
                v00 += r0.x; v01 += r0.y; v10 += r1.x; v11 += r1.y;
            }
            if (MODE == 1) {
                v00 = gelu_exact(v00); v01 = gelu_exact(v01);
                v10 = gelu_exact(v10); v11 = gelu_exact(v11);
                bf16 h0,h1,h2,h3,l0,l1,l2,l3;
                split2(v00,h0,l0); split2(v01,h1,l1);
                split2(v10,h2,l2); split2(v11,h3,l3);
                bf162 pa; pa.x=h0; pa.y=h1;  bf162 pb; pb.x=h2; pb.y=h3;
                bf162 qa; qa.x=l0; qa.y=l1;  bf162 qb; qb.x=l2; qb.y=l3;
                *(bf162*)(Chi + (size_t)r * N + c0)       = pa;
                *(bf162*)(Chi + (size_t)(r + 8) * N + c0) = pb;
                *(bf162*)(Clo + (size_t)r * N + c0)       = qa;
                *(bf162*)(Clo + (size_t)(r + 8) * N + c0) = qb;
            } else if (MODE == 3) {
                uint32_t pa = pk2(v00, v01);
                uint32_t pb = pk2(v10, v11);
                *(uint32_t*)(Chi + (size_t)r * N + c0)       = pa;
                *(uint32_t*)(Chi + (size_t)(r + 8) * N + c0) = pb;
            } else {
                *(float2*)(C + (size_t)r * N + c0)       = make_float2(v00, v01);
                *(float2*)(C + (size_t)(r + 8) * N + c0) = make_float2(v10, v11);
            }
        }
    }
}

// ---------------- tensor-core causal flash attention ------------------------
#define KSTR 72

__global__ __launch_bounds__(256) void attn_mma_kernel(
    const bf16* __restrict__ qkvb, bf16* __restrict__ o_hi, bf16* __restrict__ o_lo)
{
    extern __shared__ char asmem[];
    bf16* Qs = (bf16*)asmem;
    bf16* Ks = Qs + 128 * KSTR;
    bf16* Vs = Ks + 2 * 64 * KSTR;

    const int tid = threadIdx.x;
    const int warp = tid >> 5, lane = tid & 31;
    const int gg = lane >> 2, qt = lane & 3;
    const int g8 = lane >> 3, lr = lane & 7;
    const int qt_blk = gridDim.x - 1 - blockIdx.x;      // heavy-first
    const int bh = blockIdx.y;
    const int b = bh >> 4, h = bh & 15;
    const int q0 = qt_blk * 128;
    const size_t ROW = 3 * DMODEL;
    const bf16* qg = qkvb + (size_t)(b * SEQ) * ROW + h * HDIM;
    const bf16* kg = qg + DMODEL;
    const bf16* vg = qg + 2 * DMODEL;

    #pragma unroll
    for (int u = 0; u < 4; u++) {
        int idx = tid + u * 256;
        int r = idx >> 3, c = (idx & 7) * 8;
        *(uint4*)&Qs[r * KSTR + c] = *(const uint4*)(qg + (size_t)(q0 + r) * ROW + c);
    }
    __syncthreads();

    uint32_t qf[4][4];
    {
        const bf162 sc = __floats2bfloat162_rn(0.125f, 0.125f);
        #pragma unroll
        for (int kt = 0; kt < 4; kt++) {
            const bf16* p = &Qs[(warp * 16 + (g8 & 1) * 8 + lr) * KSTR + kt * 16 + (g8 >> 1) * 8];
            ldsm_x4(qf[kt][0], qf[kt][1], qf[kt][2], qf[kt][3], p);
            #pragma unroll
            for (int i = 0; i < 4; i++) {
                bf162 v = *(bf162*)&qf[kt][i];
                v = __hmul2(v, sc);
                qf[kt][i] = *(uint32_t*)&v;
            }
        }
    }

    float oacc[8][4];
    #pragma unroll
    for (int nt = 0; nt < 8; nt++)
        #pragma unroll
        for (int i = 0; i < 4; i++) oacc[nt][i] = 0.f;
    float m0 = -1e30f, m1 = -1e30f, l0 = 0.f, l1 = 0.f;

    const int ntiles = qt_blk * 2 + 2;
    const int wbase = q0 + warp * 16;
    const int wmax  = wbase + 15;

    auto issue = [&](int t, int st) {
        #pragma unroll
        for (int u = 0; u < 2; u++) {
            int idx = tid + u * 256;
            int r = idx >> 3, c = (idx & 7) * 8;
            size_t goff = (size_t)(t * 64 + r) * ROW + c;
            cp16(&Ks[st * 64 * KSTR + r * KSTR + c], kg + goff);
            cp16(&Vs[st * 64 * KSTR + r * KSTR + c], vg + goff);
        }
    };

    issue(0, 0); cp_commit();

    for (int t = 0; t < ntiles; t++) {
        const int cur = t & 1;
        if (t + 1 < ntiles) { issue(t + 1, cur ^ 1); cp_commit(); cp_wait<1>(); }
        else                { cp_wait<0>(); }
        __syncthreads();

        const int j0 = t * 64;
        if (j0 <= wmax) {
            const bf16* Kt = &Ks[cur * 64 * KSTR];
            const bf16* Vt = &Vs[cur * 64 * KSTR];

            float sacc[8][4];
            #pragma unroll
            for (int nt = 0; nt < 8; nt++)
                #pragma unroll
                for (int i = 0; i < 4; i++) sacc[nt][i] = 0.f;

            #pragma unroll
            for (int kt = 0; kt < 4; kt++) {
                uint32_t bfr[8][2];
                #pragma unroll
                for (int np = 0; np < 4; np++) {
                    const bf16* p = &Kt[(np * 16 + (g8 >> 1) * 8 + lr) * KSTR + kt * 16 + (g8 & 1) * 8];
                    ldsm_x4(bfr[2*np][0], bfr[2*np][1], bfr[2*np+1][0], bfr[2*np+1][1], p);
                }
                #pragma unroll
                for (int nt = 0; nt < 8; nt++)
                    mma16816(sacc[nt], qf[kt], bfr[nt]);
            }

            const int r0 = wbase + gg, r1 = r0 + 8;
            if (j0 + 63 > wbase) {
                #pragma unroll
                for (int nt = 0; nt < 8; nt++) {
                    int c0 = j0 + nt * 8 + 2 * qt, c1 = c0 + 1;
                    if (c0 > r0) sacc[nt][0] = -1e30f;
                    if (c1 > r0) sacc[nt][1] = -1e30f;
                    if (c0 > r1) sacc[nt][2] = -1e30f;
                    if (c1 > r1) sacc[nt][3] = -1e30f;
                }
            }

            float mx0 = -1e30f, mx1 = -1e30f;
            #pragma unroll
            for (int nt = 0; nt < 8; nt++) {
                mx0 = fmaxf(mx0, fmaxf(sacc[nt][0], sacc[nt][1]));
                mx1 = fmaxf(mx1, fmaxf(sacc[nt][2], sacc[nt][3]));
            }
            mx0 = fmaxf(mx0, __shfl_xor_sync(0xffffffffu, mx0, 1));
            mx0 = fmaxf(mx0, __shfl_xor_sync(0xffffffffu, mx0, 2));
            mx1 = fmaxf(mx1, __shfl_xor_sync(0xffffffffu, mx1, 1));
            mx1 = fmaxf(mx1, __shfl_xor_sync(0xffffffffu, mx1, 2));
            float mn0 = fmaxf(m0, mx0), mn1 = fmaxf(m1, mx1);
            float cr0 = __expf(m0 - mn0), cr1 = __expf(m1 - mn1);
            m0 = mn0; m1 = mn1;

            float ps0 = 0.f, ps1 = 0.f;
            uint32_t pa[4][4];
            #pragma unroll
            for (int np = 0; np < 4; np++) {
                float e00 = __expf(sacc[2*np  ][0] - mn0);
                float e01 = __expf(sacc[2*np  ][1] - mn0);
                float e02 = __expf(sacc[2*np  ][2] - mn1);
                float e03 = __expf(sacc[2*np  ][3] - mn1);
                float e10 = __expf(sacc[2*np+1][0] - mn0);
                float e11 = __expf(sacc[2*np+1][1] - mn0);
                float e12 = __expf(sacc[2*np+1][2] - mn1);
                float e13 = __expf(sacc[2*np+1][3] - mn1);
                ps0 += e00 + e01 + e10 + e11;
                ps1 += e02 + e03 + e12 + e13;
                pa[np][0] = pk2(e00, e01);
                pa[np][1] = pk2(e02, e03);
                pa[np][2] = pk2(e10, e11);
                pa[np][3] = pk2(e12, e13);
            }
            ps0 += __shfl_xor_sync(0xffffffffu, ps0, 1);
            ps0 += __shfl_xor_sync(0xffffffffu, ps0, 2);
            ps1 += __shfl_xor_sync(0xffffffffu, ps1, 1);
            ps1 += __shfl_xor_sync(0xffffffffu, ps1, 2);
            l0 = l0 * cr0 + ps0;
            l1 = l1 * cr1 + ps1;
            #pragma unroll
            for (int nt = 0; nt < 8; nt++) {
                oacc[nt][0] *= cr0; oacc[nt][1] *= cr0;
                oacc[nt][2] *= cr1; oacc[nt][3] *= cr1;
            }

            #pragma unroll
            for (int kt = 0; kt < 4; kt++) {
                uint32_t vfr[8][2];
                #pragma unroll
                for (int np = 0; np < 4; np++) {
                    const bf16* p = &Vt[(kt * 16 + (g8 & 1) * 8 + lr) * KSTR + np * 16 + (g8 >> 1) * 8];
                    ldsm_x4_t(vfr[2*np][0], vfr[2*np][1], vfr[2*np+1][0], vfr[2*np+1][1], p);
                }
                #pragma unroll
                for (int nt = 0; nt < 8; nt++)
                    mma16816(oacc[nt], pa[kt], vfr[nt]);
            }
        }
        __syncthreads();
    }

    float inv0 = 1.f / l0, inv1 = 1.f / l1;
    int grow0 = b * SEQ + wbase + gg;
    int grow1 = grow0 + 8;
    #pragma unroll
    for (int nt = 0; nt < 8; nt++) {
        int col = h * HDIM + nt * 8 + 2 * qt;
        float v00 = oacc[nt][0] * inv0, v01 = oacc[nt][1] * inv0;
        float v10 = oacc[nt][2] * inv1, v11 = oacc[nt][3] * inv1;
        bf16 h0,h1,h2,h3,l0b,l1b,l2b,l3b;
        split2(v00,h0,l0b); split2(v01,h1,l1b);
        split2(v10,h2,l2b); split2(v11,h3,l3b);
        bf162 pa; pa.x=h0; pa.y=h1;  bf162 pb; pb.x=h2; pb.y=h3;
        bf162 qa; qa.x=l0b; qa.y=l1b; bf162 qb; qb.x=l2b; qb.y=l3b;
        *(bf162*)(o_hi + (size_t)grow0 * DMODEL + col) = pa;
        *(bf162*)(o_hi + (size_t)grow1 * DMODEL + col) = pb;
        *(bf162*)(o_lo + (size_t)grow0 * DMODEL + col) = qa;
        *(bf162*)(o_lo + (size_t)grow1 * DMODEL + col) = qb;
    }
}

// ---------------- launch ----------------
extern "C" void kernel_launch(void* const* d_in, const int* in_sizes, int n_in,
                              void* d_out, int out_size)
{
    const float* x     = (const float*)d_in[0];
    const float* ln1_g = (const float*)d_in[1];
    const float* ln1_b = (const float*)d_in[2];
    const float* qkv_w = (const float*)d_in[3];
    const float* qkv_b = (const float*)d_in[4];
    const float* out_w = (const float*)d_in[5];
    const float* out_b = (const float*)d_in[6];
    const float* ln2_g = (const float*)d_in[7];
    const float* ln2_b = (const float*)d_in[8];
    const float* fc1_w = (const float*)d_in[9];
    const float* fc1_b = (const float*)d_in[10];
    const float* fc2_w = (const float*)d_in[11];
    const float* fc2_b = (const float*)d_in[12];
    float* out = (float*)d_out;

    static bf16 *p_qkvb = nullptr;
    static bf16 *p_h_hi, *p_h_lo, *p_o_hi, *p_o_lo, *p_h2_hi, *p_h2_lo;
    static bf16 *p_wqkv_hi, *p_wout_hi, *p_wout_lo;
    static bf16 *p_wfc1_hi, *p_wfc1_lo, *p_wfc2_hi;
    static cudaStream_t s2 = nullptr;
    static cudaEvent_t e0, e_cvtq, e_cvt_all;
    if (!p_qkvb) {
        cudaGetSymbolAddress((void**)&p_qkvb,   g_qkvb);
        cudaGetSymbolAddress((void**)&p_h_hi,   g_h_hi);
        cudaGetSymbolAddress((void**)&p_h_lo,   g_h_lo);
        cudaGetSymbolAddress((void**)&p_o_hi,   g_o_hi);
        cudaGetSymbolAddress((void**)&p_o_lo,   g_o_lo);
        cudaGetSymbolAddress((void**)&p_h2_hi,  g_h2_hi);
        cudaGetSymbolAddress((void**)&p_h2_lo,  g_h2_lo);
        cudaGetSymbolAddress((void**)&p_wqkv_hi, g_wqkv_hi);
        cudaGetSymbolAddress((void**)&p_wout_hi, g_wout_hi);
        cudaGetSymbolAddress((void**)&p_wout_lo, g_wout_lo);
        cudaGetSymbolAddress((void**)&p_wfc1_hi, g_wfc1_hi);
        cudaGetSymbolAddress((void**)&p_wfc1_lo, g_wfc1_lo);
        cudaGetSymbolAddress((void**)&p_wfc2_hi, g_wfc2_hi);
        cudaStreamCreateWithFlags(&s2, cudaStreamNonBlocking);
        cudaEventCreateWithFlags(&e0,        cudaEventDisableTiming);
        cudaEventCreateWithFlags(&e_cvtq,    cudaEventDisableTiming);
        cudaEventCreateWithFlags(&e_cvt_all, cudaEventDisableTiming);
    }

    const int SMEM_G3 = 2 * (4 * TILE_B);                 // 81920
    const int SMEM_G2 = 2 * (3 * TILE_B);                 // 61440
    const int SMEM_G1 = 2 * (2 * TILE_B);                 // 40960
    const int SMEM_ATTN = (128 + 2*64 + 2*64) * KSTR * 2; // 55296
    cudaFuncSetAttribute((const void*)gemm_bf16x3<1,3>, cudaFuncAttributeMaxDynamicSharedMemorySize, SMEM_G3);
    cudaFuncSetAttribute((const void*)gemm_bf16x3<2,3>, cudaFuncAttributeMaxDynamicSharedMemorySize, SMEM_G3);
    cudaFuncSetAttribute((const void*)gemm_bf16x3<2,2>, cudaFuncAttributeMaxDynamicSharedMemorySize, SMEM_G2);
    cudaFuncSetAttribute((const void*)gemm_bf16x3<3,1>, cudaFuncAttributeMaxDynamicSharedMemorySize, SMEM_G1);
    cudaFuncSetAttribute((const void*)attn_mma_kernel,  cudaFuncAttributeMaxDynamicSharedMemorySize, SMEM_ATTN);

    // ---- fork: weight converts on side stream (off the critical path) ----
    cudaEventRecord(e0, 0);
    cudaStreamWaitEvent(s2, e0, 0);
    cvt_kernel<<<(3*DMODEL*DMODEL)/4/256, 256, 0, s2>>>(qkv_w, p_wqkv_hi);
    cudaEventRecord(e_cvtq, s2);
    split_kernel<<<(DMODEL*DMODEL)/4/256, 256, 0, s2>>>(out_w, p_wout_hi, p_wout_lo);
    split_kernel<<<(DFF*DMODEL)/4/256,    256, 0, s2>>>(fc1_w, p_wfc1_hi, p_wfc1_lo);
    cvt_kernel  <<<(DMODEL*DFF)/4/256,    256, 0, s2>>>(fc2_w, p_wfc2_hi);
    cudaEventRecord(e_cvt_all, s2);

    // ---- main stream: critical path ----
    layernorm_split_kernel<false><<<MROWS/2, 256>>>(x, ln1_g, ln1_b, p_h_hi, nullptr);
    cudaStreamWaitEvent(0, e_cvtq, 0);
    gemm_bf16x3<3,1><<<dim3(3*DMODEL/BN, MROWS/BM), 256, SMEM_G1>>>(
        p_h_hi, nullptr, p_wqkv_hi, nullptr, qkv_b, nullptr,
        nullptr, p_qkvb, nullptr, MROWS, 3*DMODEL, DMODEL);
    attn_mma_kernel<<<dim3(SEQ/128, BATCH*NHEADS), 256, SMEM_ATTN>>>(p_qkvb, p_o_hi, p_o_lo);
    cudaStreamWaitEvent(0, e_cvt_all, 0);
    gemm_bf16x3<2,3><<<dim3(DMODEL/BN, MROWS/BM), 256, SMEM_G3>>>(
        p_o_hi, p_o_lo, p_wout_hi, p_wout_lo, out_b, x,
        out, nullptr, nullptr, MROWS, DMODEL, DMODEL);
    layernorm_split_kernel<true><<<MROWS/2, 256>>>(out, ln2_g, ln2_b, p_h_hi, p_h_lo);
    gemm_bf16x3<1,3><<<dim3(DFF/BN, MROWS/BM), 256, SMEM_G3>>>(
        p_h_hi, p_h_lo, p_wfc1_hi, p_wfc1_lo, fc1_b, nullptr,
        nullptr, p_h2_hi, p_h2_lo, MROWS, DFF, DMODEL);
    gemm_bf16x3<2,2><<<dim3(DMODEL/BN, MROWS/BM), 256, SMEM_G2>>>(
        p_h2_hi, p_h2_lo, p_wfc2_hi, nullptr, fc2_b, out,
        out, nullptr, nullptr, MROWS, DMODEL, DFF);
}